// round 5
// baseline (speedup 1.0000x reference)
#include <cuda_runtime.h>
#include <cuda_fp16.h>
#include <cstdint>

// ---------------- problem constants ----------------
static constexpr int K_DIM   = 1024;
static constexpr int N_DIM   = 3072;       // 3*DIM
static constexpr int M_TOT   = 8 * 4096;   // 32768 rows
static constexpr int POOL_RK = 8;

// GEMM tiling: CTA 256x128, warp tile 64x64 (8 warps: 4 in M x 2 in N)
static constexpr int TM = 256;
static constexpr int TN = 128;
static constexpr int KC = 64;              // fp16 K per chunk
static constexpr int NK = K_DIM / KC;      // 16 chunks
static constexpr int NSTAGE = 4;

// SMEM: padded rows, 64+8 halves = 144 bytes stride
static constexpr int ROW_HALF = KC + 8;                    // 72
static constexpr int ROW_B    = ROW_HALF * 2;              // 144
static constexpr int A_TILE_B = TM * ROW_B;                // 36864
static constexpr int B_TILE_B = TN * ROW_B;                // 18432
static constexpr int STAGE_B  = A_TILE_B + B_TILE_B;       // 55296
static constexpr int SM_BIAS  = 0;                         // 128 f32
static constexpr int SM_EPB   = 512;                       // 8*128 f32
static constexpr int SM_STAGE = 4608;
static constexpr int SM_TOTAL = SM_STAGE + NSTAGE * STAGE_B;  // 225792 (~220.5 KB)
static_assert(SM_TOTAL <= 232448, "exceeds sm_100a max dynamic smem per block");

// ---------------- device scratch ----------------
__device__ __half g_xh[(size_t)M_TOT * K_DIM];   // 64 MB
__device__ __half g_wh[(size_t)N_DIM * K_DIM];   //  6 MB
__device__ float  g_T[(size_t)M_TOT * 16];       //  2 MB (0..7 = q, 8..15 = v)

// ---------------- PTX helpers (baseline sm_80+ PTX only) ----------------
__device__ __forceinline__ uint32_t smem_u32(const void* p) {
    return (uint32_t)__cvta_generic_to_shared(p);
}
__device__ __forceinline__ void cp_async16(uint32_t dst, const void* src) {
    asm volatile("cp.async.cg.shared.global [%0], [%1], 16;"
                 :: "r"(dst), "l"(__cvta_generic_to_global(src)));
}
#define CP_COMMIT() asm volatile("cp.async.commit_group;" ::: "memory")
template <int N> __device__ __forceinline__ void cp_wait() {
    asm volatile("cp.async.wait_group %0;" :: "n"(N) : "memory");
}
__device__ __forceinline__ void ldm_x4(uint32_t& r0, uint32_t& r1, uint32_t& r2, uint32_t& r3,
                                       uint32_t addr) {
    asm volatile("ldmatrix.sync.aligned.m8n8.x4.shared.b16 {%0,%1,%2,%3}, [%4];"
                 : "=r"(r0), "=r"(r1), "=r"(r2), "=r"(r3) : "r"(addr));
}
__device__ __forceinline__ void mma16816(float* c, const uint32_t* a, const uint32_t* b) {
    asm volatile(
        "mma.sync.aligned.m16n8k16.row.col.f32.f16.f16.f32 "
        "{%0,%1,%2,%3}, {%4,%5,%6,%7}, {%8,%9}, {%0,%1,%2,%3};"
        : "+f"(c[0]), "+f"(c[1]), "+f"(c[2]), "+f"(c[3])
        : "r"(a[0]), "r"(a[1]), "r"(a[2]), "r"(a[3]), "r"(b[0]), "r"(b[1]));
}

// ---------------- W convert ----------------
__global__ void cvt_w_kernel(const float* __restrict__ src) {
    size_t i = (size_t)blockIdx.x * blockDim.x + threadIdx.x;
    const size_t n4 = (size_t)N_DIM * K_DIM / 4;
    if (i < n4) {
        float4 v = ((const float4*)src)[i];
        ((__half2*)g_wh)[2 * i]     = __floats2half2_rn(v.x, v.y);
        ((__half2*)g_wh)[2 * i + 1] = __floats2half2_rn(v.z, v.w);
    }
}

// ---------------- fused x convert + LoRA T ----------------
// warp per row m: writes g_xh[m,:] (fp16) and T[m,0:8]=x@A_q[i], T[m,8:16]=x@A_v[i]
__global__ void cvt_lora_kernel(const float* __restrict__ x,
                                const float* __restrict__ Aq_pool,
                                const float* __restrict__ Av_pool,
                                const int* __restrict__ idx) {
    int warp = (blockIdx.x * blockDim.x + threadIdx.x) >> 5;
    int lid  = threadIdx.x & 31;
    if (warp >= M_TOT) return;
    const size_t m = (size_t)warp;
    const int i = idx[m >> 12];
    const float* aq = Aq_pool + (size_t)i * K_DIM * POOL_RK;
    const float* av = Av_pool + (size_t)i * K_DIM * POOL_RK;
    const float* xr = x + m * K_DIM;
    __half* xh = g_xh + m * K_DIM;

    float acc[16];
#pragma unroll
    for (int r = 0; r < 16; r++) acc[r] = 0.f;

    for (int k0 = lid * 4; k0 < K_DIM; k0 += 128) {
        float4 xv = *(const float4*)(xr + k0);
        __half2 h0 = __floats2half2_rn(xv.x, xv.y);
        __half2 h1 = __floats2half2_rn(xv.z, xv.w);
        float2 pk;
        pk.x = __uint_as_float(*(const uint32_t*)&h0);
        pk.y = __uint_as_float(*(const uint32_t*)&h1);
        *(float2*)(xh + k0) = pk;

        const float kx[4] = {xv.x, xv.y, xv.z, xv.w};
#pragma unroll
        for (int d = 0; d < 4; d++) {
            const float s = kx[d];
            const size_t kk = (size_t)(k0 + d) * 8;
            float4 a0 = *(const float4*)(aq + kk);
            float4 a1 = *(const float4*)(aq + kk + 4);
            float4 v0 = *(const float4*)(av + kk);
            float4 v1 = *(const float4*)(av + kk + 4);
            acc[0]  += s * a0.x; acc[1]  += s * a0.y; acc[2]  += s * a0.z; acc[3]  += s * a0.w;
            acc[4]  += s * a1.x; acc[5]  += s * a1.y; acc[6]  += s * a1.z; acc[7]  += s * a1.w;
            acc[8]  += s * v0.x; acc[9]  += s * v0.y; acc[10] += s * v0.z; acc[11] += s * v0.w;
            acc[12] += s * v1.x; acc[13] += s * v1.y; acc[14] += s * v1.z; acc[15] += s * v1.w;
        }
    }
#pragma unroll
    for (int r = 0; r < 16; r++) {
        float s = acc[r];
        s += __shfl_xor_sync(0xffffffffu, s, 16);
        s += __shfl_xor_sync(0xffffffffu, s, 8);
        s += __shfl_xor_sync(0xffffffffu, s, 4);
        s += __shfl_xor_sync(0xffffffffu, s, 2);
        s += __shfl_xor_sync(0xffffffffu, s, 1);
        acc[r] = s;
    }
    if (lid == 0) {
        float4* o = (float4*)(g_T + m * 16);
        o[0] = make_float4(acc[0],  acc[1],  acc[2],  acc[3]);
        o[1] = make_float4(acc[4],  acc[5],  acc[6],  acc[7]);
        o[2] = make_float4(acc[8],  acc[9],  acc[10], acc[11]);
        o[3] = make_float4(acc[12], acc[13], acc[14], acc[15]);
    }
}

// ---------------- main GEMM ----------------
// Loads one KC=64 chunk: A rows 0..255 (x), B rows 0..127 (W) into a padded stage.
__device__ __forceinline__ void load_chunk(char* stage, int m0, int n0, int kc) {
    const int t = threadIdx.x;
    const int col0 = kc * KC;
    uint32_t sA = smem_u32(stage);
    uint32_t sB = sA + A_TILE_B;
    // A: 256 rows x 8 segs = 2048 16B-ops; 8 per thread
#pragma unroll
    for (int i = 0; i < 8; i++) {
        int j   = t + i * 256;
        int row = j >> 3;
        int seg = j & 7;
        uint32_t off = (uint32_t)(row * ROW_B + seg * 16);
        cp_async16(sA + off, g_xh + (size_t)(m0 + row) * K_DIM + col0 + seg * 8);
    }
    // B: 128 rows x 8 segs = 1024 16B-ops; 4 per thread
#pragma unroll
    for (int i = 0; i < 4; i++) {
        int j   = t + i * 256;
        int row = j >> 3;
        int seg = j & 7;
        uint32_t off = (uint32_t)(row * ROW_B + seg * 16);
        cp_async16(sB + off, g_wh + (size_t)(n0 + row) * K_DIM + col0 + seg * 8);
    }
}

__global__ void __launch_bounds__(256, 1)
gemm_kernel(const float* __restrict__ bias,
            const float* __restrict__ Bq_pool,
            const float* __restrict__ Bv_pool,
            const int* __restrict__ idx,
            float* __restrict__ out) {
    extern __shared__ char smem[];
    const int tid = threadIdx.x;
    const int wid = tid >> 5;
    const int lid = tid & 31;
    const int wm  = wid & 3;       // 4 warps in M  (64 rows each)
    const int wn  = wid >> 2;      // 2 warps in N  (64 cols each)
    const int n0  = blockIdx.x * TN;
    const int m0  = blockIdx.y * TM;
    const int region = blockIdx.x >> 3;   // 0=q, 1=k, 2=v

    // ---- epilogue constants (consumed after loop; loop barriers order) ----
    float* sh_bias = (float*)(smem + SM_BIAS);
    float* sh_B    = (float*)(smem + SM_EPB);
    if (tid < 128) sh_bias[tid] = bias[n0 + tid];
    const int pool_i = idx[blockIdx.y >> 4];   // 16 M-tiles (256 rows) per batch
    if (region != 1) {
        const float* Bp = (region == 0) ? (Bq_pool + (size_t)pool_i * POOL_RK * K_DIM)
                                        : (Bv_pool + (size_t)pool_i * POOL_RK * K_DIM);
        int colbase = (region == 0) ? n0 : (n0 - 2048);
#pragma unroll
        for (int e = tid; e < 1024; e += 256) {
            int r = e >> 7, c = e & 127;
            sh_B[e] = Bp[(size_t)r * K_DIM + colbase + c];
        }
    }

    // ---- accumulators: 4 m-frags x 8 n8-frags x 4 ----
    float acc[4][8][4];
#pragma unroll
    for (int i = 0; i < 4; i++)
#pragma unroll
        for (int j = 0; j < 8; j++)
#pragma unroll
            for (int c = 0; c < 4; c++) acc[i][j][c] = 0.f;

    // per-thread ldmatrix source offsets
    const int a_row = (lid & 15);
    const int a_kh  = (lid >> 4) * 8;
    const int b_row = (lid & 7) + ((lid >> 4) << 3);
    const int b_kh  = ((lid >> 3) & 1) * 8;

    // ---- pipeline prologue: 3 stages in flight ----
    load_chunk(smem + SM_STAGE + 0 * STAGE_B, m0, n0, 0); CP_COMMIT();
    load_chunk(smem + SM_STAGE + 1 * STAGE_B, m0, n0, 1); CP_COMMIT();
    load_chunk(smem + SM_STAGE + 2 * STAGE_B, m0, n0, 2); CP_COMMIT();

    // ---- main K loop: ONE barrier per iteration ----
    for (int kc = 0; kc < NK; kc++) {
        if (kc < NK - 2)       cp_wait<2>();
        else if (kc == NK - 2) cp_wait<1>();
        else                   cp_wait<0>();
        __syncthreads();
        // All warps finished reading stage (kc-1)&3 == (kc+3)&3 -> safe to refill.

        int kn = kc + 3;
        if (kn < NK) {
            load_chunk(smem + SM_STAGE + (kn & 3) * STAGE_B, m0, n0, kn);
            CP_COMMIT();
        }

        char* stage = smem + SM_STAGE + (kc & 3) * STAGE_B;
        uint32_t sA = smem_u32(stage);
        uint32_t sB = sA + A_TILE_B;
#pragma unroll
        for (int ks = 0; ks < 4; ks++) {
            const int k0 = ks * 16;
            uint32_t a[4][4];
#pragma unroll
            for (int am = 0; am < 4; am++) {
                uint32_t addr = sA + (uint32_t)((wm * 64 + am * 16 + a_row) * ROW_B
                                                + (k0 + a_kh) * 2);
                ldm_x4(a[am][0], a[am][1], a[am][2], a[am][3], addr);
            }
            uint32_t b[4][4];
#pragma unroll
            for (int g = 0; g < 4; g++) {
                uint32_t addr = sB + (uint32_t)((wn * 64 + g * 16 + b_row) * ROW_B
                                                + (k0 + b_kh) * 2);
                ldm_x4(b[g][0], b[g][1], b[g][2], b[g][3], addr);
            }
#pragma unroll
            for (int am = 0; am < 4; am++)
#pragma unroll
                for (int an = 0; an < 8; an++) {
                    uint32_t bb[2] = { b[an >> 1][(an & 1) * 2],
                                       b[an >> 1][(an & 1) * 2 + 1] };
                    mma16816(acc[am][an], a[am], bb);
                }
        }
    }

    // ---- epilogue: bias + LoRA + store ----
    const bool lora = (region != 1);
    const int tq = lid >> 2;          // 0..7
    const int tr = lid & 3;           // 0..3
#pragma unroll
    for (int am = 0; am < 4; am++) {
#pragma unroll
        for (int h = 0; h < 2; h++) {
            const int lrow = wm * 64 + am * 16 + tq + h * 8;
            const size_t m = (size_t)(m0 + lrow);
            float t[8];
            if (lora) {
                const float* Tp = g_T + m * 16 + (region == 2 ? 8 : 0);
                float4 t0 = *(const float4*)Tp;
                float4 t1 = *(const float4*)(Tp + 4);
                t[0] = t0.x; t[1] = t0.y; t[2] = t0.z; t[3] = t0.w;
                t[4] = t1.x; t[5] = t1.y; t[6] = t1.z; t[7] = t1.w;
            }
#pragma unroll
            for (int an = 0; an < 8; an++) {
                const int lc = wn * 64 + an * 8 + tr * 2;
                float v0 = acc[am][an][h * 2 + 0] + sh_bias[lc];
                float v1 = acc[am][an][h * 2 + 1] + sh_bias[lc + 1];
                if (lora) {
#pragma unroll
                    for (int rr = 0; rr < 8; rr++) {
                        v0 += t[rr] * sh_B[rr * 128 + lc];
                        v1 += t[rr] * sh_B[rr * 128 + lc + 1];
                    }
                }
                *(float2*)(out + m * N_DIM + n0 + lc) = make_float2(v0, v1);
            }
        }
    }
}

// ---------------- launch ----------------
extern "C" void kernel_launch(void* const* d_in, const int* in_sizes, int n_in,
                              void* d_out, int out_size) {
    (void)in_sizes; (void)n_in; (void)out_size;
    const float* x    = (const float*)d_in[0];
    const float* w    = (const float*)d_in[1];
    const float* bias = (const float*)d_in[2];
    const float* Aq   = (const float*)d_in[3];
    const float* Bq   = (const float*)d_in[4];
    const float* Av   = (const float*)d_in[5];
    const float* Bv   = (const float*)d_in[6];
    const int*   idx  = (const int*)d_in[7];
    float* out = (float*)d_out;

    static bool attr_set = false;
    if (!attr_set) {
        cudaFuncSetAttribute(gemm_kernel, cudaFuncAttributeMaxDynamicSharedMemorySize,
                             SM_TOTAL);
        attr_set = true;
    }

    const size_t w4 = (size_t)N_DIM * K_DIM / 4;
    cvt_w_kernel<<<(unsigned)((w4 + 255) / 256), 256>>>(w);
    cvt_lora_kernel<<<M_TOT / 8, 256>>>(x, Aq, Av, idx);

    dim3 grid(N_DIM / TN, M_TOT / TM, 1);
    gemm_kernel<<<grid, 256, SM_TOTAL>>>(bias, Bq, Bv, idx, out);
}

// round 6
// speedup vs baseline: 1.1677x; 1.1677x over previous
#include <cuda_runtime.h>
#include <cuda_fp16.h>
#include <cstdint>

// ---------------- problem constants ----------------
static constexpr int K_DIM   = 1024;
static constexpr int N_DIM   = 3072;       // 3*DIM
static constexpr int M_TOT   = 8 * 4096;   // 32768 rows
static constexpr int POOL_RK = 8;

// GEMM tiling (R2 config: best measured)
static constexpr int TM = 128;
static constexpr int TN = 128;
static constexpr int KC = 64;              // fp16 K per chunk
static constexpr int NK = K_DIM / KC;      // 16 chunks
static constexpr int NSTAGE = 3;

// SMEM: padded rows, 64+8 halves = 144 bytes stride
static constexpr int ROW_HALF = KC + 8;                    // 72
static constexpr int ROW_B    = ROW_HALF * 2;              // 144
static constexpr int TILE_B   = TM * ROW_B;                // 18432 per matrix
static constexpr int STAGE_B  = 2 * TILE_B;                // 36864
static constexpr int SM_BIAS  = 0;                         // 128 f32
static constexpr int SM_EPB   = 512;                       // 8*128 f32
static constexpr int SM_STAGE = 4608;
static constexpr int SM_TOTAL = SM_STAGE + NSTAGE * STAGE_B;  // 115200

// ---------------- device scratch ----------------
__device__ __half g_xh[(size_t)M_TOT * K_DIM];   // 64 MB
__device__ __half g_wh[(size_t)N_DIM * K_DIM];   //  6 MB
__device__ float  g_T[(size_t)M_TOT * 16];       //  2 MB (0..7 = q, 8..15 = v)

// ---------------- PTX helpers (baseline sm_80+ PTX only) ----------------
__device__ __forceinline__ uint32_t smem_u32(const void* p) {
    return (uint32_t)__cvta_generic_to_shared(p);
}
__device__ __forceinline__ void cp_async16(uint32_t dst, const void* src) {
    asm volatile("cp.async.cg.shared.global [%0], [%1], 16;"
                 :: "r"(dst), "l"(__cvta_generic_to_global(src)));
}
#define CP_COMMIT() asm volatile("cp.async.commit_group;" ::: "memory")
template <int N> __device__ __forceinline__ void cp_wait() {
    asm volatile("cp.async.wait_group %0;" :: "n"(N) : "memory");
}
__device__ __forceinline__ void ldm_x4(uint32_t& r0, uint32_t& r1, uint32_t& r2, uint32_t& r3,
                                       uint32_t addr) {
    asm volatile("ldmatrix.sync.aligned.m8n8.x4.shared.b16 {%0,%1,%2,%3}, [%4];"
                 : "=r"(r0), "=r"(r1), "=r"(r2), "=r"(r3) : "r"(addr));
}
__device__ __forceinline__ void mma16816(float* c, const uint32_t* a, const uint32_t* b) {
    asm volatile(
        "mma.sync.aligned.m16n8k16.row.col.f32.f16.f16.f32 "
        "{%0,%1,%2,%3}, {%4,%5,%6,%7}, {%8,%9}, {%0,%1,%2,%3};"
        : "+f"(c[0]), "+f"(c[1]), "+f"(c[2]), "+f"(c[3])
        : "r"(a[0]), "r"(a[1]), "r"(a[2]), "r"(a[3]), "r"(b[0]), "r"(b[1]));
}

// ---------------- W convert ----------------
__global__ void cvt_w_kernel(const float* __restrict__ src) {
    size_t i = (size_t)blockIdx.x * blockDim.x + threadIdx.x;
    const size_t n4 = (size_t)N_DIM * K_DIM / 4;
    if (i < n4) {
        float4 v = ((const float4*)src)[i];
        ((__half2*)g_wh)[2 * i]     = __floats2half2_rn(v.x, v.y);
        ((__half2*)g_wh)[2 * i + 1] = __floats2half2_rn(v.z, v.w);
    }
}

// ---------------- fused x convert + LoRA T: 4 rows per warp ----------------
// warp handles rows m0..m0+3: writes g_xh fp16 and T[m,0:8]=x@A_q, T[m,8:16]=x@A_v.
// A-pool fragments are loaded ONCE per k-position and reused across the 4 rows.
__global__ void cvt_lora_kernel(const float* __restrict__ x,
                                const float* __restrict__ Aq_pool,
                                const float* __restrict__ Av_pool,
                                const int* __restrict__ idx) {
    const int warp = (blockIdx.x * blockDim.x + threadIdx.x) >> 5;
    const int lid  = threadIdx.x & 31;
    if (warp >= M_TOT / 4) return;
    const int m0 = warp * 4;
    const int i  = idx[m0 >> 12];
    const float* aq = Aq_pool + (size_t)i * K_DIM * POOL_RK;
    const float* av = Av_pool + (size_t)i * K_DIM * POOL_RK;

    float acc[4][16];
#pragma unroll
    for (int r = 0; r < 4; r++)
#pragma unroll
        for (int j = 0; j < 16; j++) acc[r][j] = 0.f;

    for (int k0 = lid * 4; k0 < K_DIM; k0 += 128) {   // 8 iterations
        float4 xv[4];
#pragma unroll
        for (int r = 0; r < 4; r++) {
            xv[r] = *(const float4*)(x + (size_t)(m0 + r) * K_DIM + k0);
            __half2 h0 = __floats2half2_rn(xv[r].x, xv[r].y);
            __half2 h1 = __floats2half2_rn(xv[r].z, xv[r].w);
            float2 pk;
            pk.x = __uint_as_float(*(const uint32_t*)&h0);
            pk.y = __uint_as_float(*(const uint32_t*)&h1);
            *(float2*)(g_xh + (size_t)(m0 + r) * K_DIM + k0) = pk;
        }
#pragma unroll
        for (int d = 0; d < 4; d++) {
            const size_t kk = (size_t)(k0 + d) * 8;
            float4 a0 = *(const float4*)(aq + kk);
            float4 a1 = *(const float4*)(aq + kk + 4);
            float4 v0 = *(const float4*)(av + kk);
            float4 v1 = *(const float4*)(av + kk + 4);
#pragma unroll
            for (int r = 0; r < 4; r++) {
                const float s = (d == 0) ? xv[r].x : (d == 1) ? xv[r].y
                              : (d == 2) ? xv[r].z : xv[r].w;
                acc[r][0]  += s * a0.x; acc[r][1]  += s * a0.y;
                acc[r][2]  += s * a0.z; acc[r][3]  += s * a0.w;
                acc[r][4]  += s * a1.x; acc[r][5]  += s * a1.y;
                acc[r][6]  += s * a1.z; acc[r][7]  += s * a1.w;
                acc[r][8]  += s * v0.x; acc[r][9]  += s * v0.y;
                acc[r][10] += s * v0.z; acc[r][11] += s * v0.w;
                acc[r][12] += s * v1.x; acc[r][13] += s * v1.y;
                acc[r][14] += s * v1.z; acc[r][15] += s * v1.w;
            }
        }
    }
#pragma unroll
    for (int r = 0; r < 4; r++) {
#pragma unroll
        for (int j = 0; j < 16; j++) {
            float s = acc[r][j];
            s += __shfl_xor_sync(0xffffffffu, s, 16);
            s += __shfl_xor_sync(0xffffffffu, s, 8);
            s += __shfl_xor_sync(0xffffffffu, s, 4);
            s += __shfl_xor_sync(0xffffffffu, s, 2);
            s += __shfl_xor_sync(0xffffffffu, s, 1);
            acc[r][j] = s;
        }
        if (lid == 0) {
            float4* o = (float4*)(g_T + (size_t)(m0 + r) * 16);
            o[0] = make_float4(acc[r][0],  acc[r][1],  acc[r][2],  acc[r][3]);
            o[1] = make_float4(acc[r][4],  acc[r][5],  acc[r][6],  acc[r][7]);
            o[2] = make_float4(acc[r][8],  acc[r][9],  acc[r][10], acc[r][11]);
            o[3] = make_float4(acc[r][12], acc[r][13], acc[r][14], acc[r][15]);
        }
    }
}

// ---------------- main GEMM ----------------
__device__ __forceinline__ void load_chunk(char* stage, int m0, int n0, int kc) {
    const int t = threadIdx.x;
    const int col0 = kc * KC;
    uint32_t sA = smem_u32(stage);
    uint32_t sB = sA + TILE_B;
#pragma unroll
    for (int i = 0; i < 4; i++) {
        int j   = t + i * 256;      // 0..1023 : 16B segments of a 128x64 fp16 tile
        int row = j >> 3;
        int seg = j & 7;
        uint32_t off = (uint32_t)(row * ROW_B + seg * 16);
        cp_async16(sA + off, g_xh + (size_t)(m0 + row) * K_DIM + col0 + seg * 8);
        cp_async16(sB + off, g_wh + (size_t)(n0 + row) * K_DIM + col0 + seg * 8);
    }
}

// load ldmatrix fragments for k16-step `ks_` into buffer `buf_`
#define LDFR(buf_, ks_) do {                                                       \
    const int k0_ = (ks_) * 16;                                                    \
    _Pragma("unroll")                                                              \
    for (int am = 0; am < 4; am++) {                                               \
        uint32_t ad_ = sA + (uint32_t)((wm * 64 + am * 16 + a_row) * ROW_B         \
                                       + (k0_ + a_kh) * 2);                        \
        ldm_x4(afr[buf_][am][0], afr[buf_][am][1],                                 \
               afr[buf_][am][2], afr[buf_][am][3], ad_);                           \
    }                                                                              \
    _Pragma("unroll")                                                              \
    for (int g = 0; g < 2; g++) {                                                  \
        uint32_t bd_ = sB + (uint32_t)((wn * 32 + g * 16 + b_row) * ROW_B          \
                                       + (k0_ + b_kh) * 2);                        \
        ldm_x4(bfr[buf_][g][0], bfr[buf_][g][1],                                   \
               bfr[buf_][g][2], bfr[buf_][g][3], bd_);                             \
    }                                                                              \
} while (0)

__global__ void __launch_bounds__(256, 1)
gemm_kernel(const float* __restrict__ bias,
            const float* __restrict__ Bq_pool,
            const float* __restrict__ Bv_pool,
            const int* __restrict__ idx,
            float* __restrict__ out) {
    extern __shared__ char smem[];
    const int tid = threadIdx.x;
    const int wid = tid >> 5;
    const int lid = tid & 31;
    const int wm  = wid & 1;       // 2 warps in M  (64 rows each)
    const int wn  = wid >> 1;      // 4 warps in N  (32 cols each)
    const int n0  = blockIdx.x * TN;
    const int m0  = blockIdx.y * TM;
    const int region = blockIdx.x >> 3;   // 0=q, 1=k, 2=v

    // ---- epilogue constants ----
    float* sh_bias = (float*)(smem + SM_BIAS);
    float* sh_B    = (float*)(smem + SM_EPB);
    if (tid < 128) sh_bias[tid] = bias[n0 + tid];
    const int pool_i = idx[blockIdx.y >> 5];   // 32 M-tiles (128 rows) per batch
    if (region != 1) {
        const float* Bp = (region == 0) ? (Bq_pool + (size_t)pool_i * POOL_RK * K_DIM)
                                        : (Bv_pool + (size_t)pool_i * POOL_RK * K_DIM);
        int colbase = (region == 0) ? n0 : (n0 - 2048);
#pragma unroll
        for (int e = tid; e < 1024; e += 256) {
            int r = e >> 7, c = e & 127;
            sh_B[e] = Bp[(size_t)r * K_DIM + colbase + c];
        }
    }

    // ---- accumulators ----
    float acc[4][4][4];
#pragma unroll
    for (int i = 0; i < 4; i++)
#pragma unroll
        for (int j = 0; j < 4; j++)
#pragma unroll
            for (int c = 0; c < 4; c++) acc[i][j][c] = 0.f;

    // per-thread ldmatrix source offsets
    const int a_row = (lid & 15);
    const int a_kh  = (lid >> 4) * 8;
    const int b_row = (lid & 7) + ((lid >> 4) << 3);
    const int b_kh  = ((lid >> 3) & 1) * 8;

    // ---- pipeline prologue: 2 stages in flight ----
    load_chunk(smem + SM_STAGE + 0 * STAGE_B, m0, n0, 0); CP_COMMIT();
    load_chunk(smem + SM_STAGE + 1 * STAGE_B, m0, n0, 1); CP_COMMIT();

    // ---- main K loop: one barrier per iteration ----
    for (int kc = 0; kc < NK; kc++) {
        if (kc == NK - 1) cp_wait<0>(); else cp_wait<1>();
        __syncthreads();
        // All warps are past compute of kc-1 => stage (kc+2)%3 (read at kc-1) is free.

        int kn = kc + 2;
        if (kn < NK) {
            load_chunk(smem + SM_STAGE + (kn % NSTAGE) * STAGE_B, m0, n0, kn);
            CP_COMMIT();
        }

        char* stage = smem + SM_STAGE + (kc % NSTAGE) * STAGE_B;
        uint32_t sA = smem_u32(stage);
        uint32_t sB = sA + TILE_B;

        uint32_t afr[2][4][4];
        uint32_t bfr[2][2][4];
        LDFR(0, 0);
#pragma unroll
        for (int ks = 0; ks < 4; ks++) {
            const int cur = ks & 1;
            if (ks < 3) LDFR(cur ^ 1, ks + 1);
#pragma unroll
            for (int am = 0; am < 4; am++)
#pragma unroll
                for (int an = 0; an < 4; an++) {
                    uint32_t bb[2] = { bfr[cur][an >> 1][(an & 1) * 2],
                                       bfr[cur][an >> 1][(an & 1) * 2 + 1] };
                    mma16816(acc[am][an], afr[cur][am], bb);
                }
        }
    }

    // ---- epilogue: bias + LoRA + store ----
    const bool lora = (region != 1);
    const int tq = lid >> 2;          // 0..7
    const int tr = lid & 3;           // 0..3
#pragma unroll
    for (int am = 0; am < 4; am++) {
#pragma unroll
        for (int h = 0; h < 2; h++) {
            const int lrow = wm * 64 + am * 16 + tq + h * 8;
            const size_t m = (size_t)(m0 + lrow);
            float t[8];
            if (lora) {
                const float* Tp = g_T + m * 16 + (region == 2 ? 8 : 0);
                float4 t0 = *(const float4*)Tp;
                float4 t1 = *(const float4*)(Tp + 4);
                t[0] = t0.x; t[1] = t0.y; t[2] = t0.z; t[3] = t0.w;
                t[4] = t1.x; t[5] = t1.y; t[6] = t1.z; t[7] = t1.w;
            }
#pragma unroll
            for (int an = 0; an < 4; an++) {
                const int lc = wn * 32 + an * 8 + tr * 2;
                float v0 = acc[am][an][h * 2 + 0] + sh_bias[lc];
                float v1 = acc[am][an][h * 2 + 1] + sh_bias[lc + 1];
                if (lora) {
#pragma unroll
                    for (int rr = 0; rr < 8; rr++) {
                        v0 += t[rr] * sh_B[rr * 128 + lc];
                        v1 += t[rr] * sh_B[rr * 128 + lc + 1];
                    }
                }
                *(float2*)(out + m * N_DIM + n0 + lc) = make_float2(v0, v1);
            }
        }
    }
}

// ---------------- launch ----------------
extern "C" void kernel_launch(void* const* d_in, const int* in_sizes, int n_in,
                              void* d_out, int out_size) {
    (void)in_sizes; (void)n_in; (void)out_size;
    const float* x    = (const float*)d_in[0];
    const float* w    = (const float*)d_in[1];
    const float* bias = (const float*)d_in[2];
    const float* Aq   = (const float*)d_in[3];
    const float* Bq   = (const float*)d_in[4];
    const float* Av   = (const float*)d_in[5];
    const float* Bv   = (const float*)d_in[6];
    const int*   idx  = (const int*)d_in[7];
    float* out = (float*)d_out;

    static bool attr_set = false;
    if (!attr_set) {
        cudaFuncSetAttribute(gemm_kernel, cudaFuncAttributeMaxDynamicSharedMemorySize,
                             SM_TOTAL);
        attr_set = true;
    }

    const size_t w4 = (size_t)N_DIM * K_DIM / 4;
    cvt_w_kernel<<<(unsigned)((w4 + 255) / 256), 256>>>(w);
    cvt_lora_kernel<<<M_TOT / 4 / 8, 256>>>(x, Aq, Av, idx);

    dim3 grid(N_DIM / TN, M_TOT / TM, 1);
    gemm_kernel<<<grid, 256, SM_TOTAL>>>(bias, Bq, Bv, idx, out);
}

// round 8
// speedup vs baseline: 1.4871x; 1.2735x over previous
#include <cuda_runtime.h>
#include <cuda_fp16.h>
#include <cstdint>

// ---------------- problem constants ----------------
static constexpr int K_DIM   = 1024;
static constexpr int N_DIM   = 3072;       // 3*DIM
static constexpr int M_TOT   = 8 * 4096;   // 32768 rows
static constexpr int POOL_RK = 8;

// GEMM tiling (R2 config, 2 CTAs/SM)
static constexpr int TM = 128;
static constexpr int TN = 128;
static constexpr int KC = 64;              // fp16 K per chunk
static constexpr int NK = K_DIM / KC;      // 16 chunks
static constexpr int NSTAGE = 3;

// SMEM: padded rows, 64+8 halves = 144 bytes stride
static constexpr int ROW_HALF = KC + 8;                    // 72
static constexpr int ROW_B    = ROW_HALF * 2;              // 144
static constexpr int TILE_B   = TM * ROW_B;                // 18432 per matrix
static constexpr int STAGE_B  = 2 * TILE_B;                // 36864
static constexpr int SM_BIAS  = 0;                         // 128 f32
static constexpr int SM_EPB   = 512;                       // 8*128 f32
static constexpr int SM_STAGE = 4608;
static constexpr int SM_TOTAL = SM_STAGE + NSTAGE * STAGE_B;  // 115200 (x2 = 225 KB/SM)

// ---------------- device scratch ----------------
__device__ __half g_xh[(size_t)M_TOT * K_DIM];   // 64 MB
__device__ __half g_wh[(size_t)N_DIM * K_DIM];   //  6 MB
__device__ float  g_T[(size_t)M_TOT * 16];       //  2 MB (0..7 = q, 8..15 = v)

// ---------------- PTX helpers (baseline sm_80+ PTX only) ----------------
__device__ __forceinline__ uint32_t smem_u32(const void* p) {
    return (uint32_t)__cvta_generic_to_shared(p);
}
__device__ __forceinline__ void cp_async16(uint32_t dst, const void* src) {
    asm volatile("cp.async.cg.shared.global [%0], [%1], 16;"
                 :: "r"(dst), "l"(__cvta_generic_to_global(src)));
}
#define CP_COMMIT() asm volatile("cp.async.commit_group;" ::: "memory")
template <int N> __device__ __forceinline__ void cp_wait() {
    asm volatile("cp.async.wait_group %0;" :: "n"(N) : "memory");
}
__device__ __forceinline__ void ldm_x4(uint32_t& r0, uint32_t& r1, uint32_t& r2, uint32_t& r3,
                                       uint32_t addr) {
    asm volatile("ldmatrix.sync.aligned.m8n8.x4.shared.b16 {%0,%1,%2,%3}, [%4];"
                 : "=r"(r0), "=r"(r1), "=r"(r2), "=r"(r3) : "r"(addr));
}
__device__ __forceinline__ void mma16816(float* c, const uint32_t* a, const uint32_t* b) {
    asm volatile(
        "mma.sync.aligned.m16n8k16.row.col.f32.f16.f16.f32 "
        "{%0,%1,%2,%3}, {%4,%5,%6,%7}, {%8,%9}, {%0,%1,%2,%3};"
        : "+f"(c[0]), "+f"(c[1]), "+f"(c[2]), "+f"(c[3])
        : "r"(a[0]), "r"(a[1]), "r"(a[2]), "r"(a[3]), "r"(b[0]), "r"(b[1]));
}

// ---------------- W convert ----------------
__global__ void cvt_w_kernel(const float* __restrict__ src) {
    size_t i = (size_t)blockIdx.x * blockDim.x + threadIdx.x;
    const size_t n4 = (size_t)N_DIM * K_DIM / 4;
    if (i < n4) {
        float4 v = ((const float4*)src)[i];
        ((__half2*)g_wh)[2 * i]     = __floats2half2_rn(v.x, v.y);
        ((__half2*)g_wh)[2 * i + 1] = __floats2half2_rn(v.z, v.w);
    }
}

// ---------------- fused x convert + LoRA T: 4 rows per warp ----------------
__global__ void cvt_lora_kernel(const float* __restrict__ x,
                                const float* __restrict__ Aq_pool,
                                const float* __restrict__ Av_pool,
                                const int* __restrict__ idx) {
    const int warp = (blockIdx.x * blockDim.x + threadIdx.x) >> 5;
    const int lid  = threadIdx.x & 31;
    if (warp >= M_TOT / 4) return;
    const int m0 = warp * 4;
    const int i  = idx[m0 >> 12];
    const float* aq = Aq_pool + (size_t)i * K_DIM * POOL_RK;
    const float* av = Av_pool + (size_t)i * K_DIM * POOL_RK;

    float acc[4][16];
#pragma unroll
    for (int r = 0; r < 4; r++)
#pragma unroll
        for (int j = 0; j < 16; j++) acc[r][j] = 0.f;

    for (int k0 = lid * 4; k0 < K_DIM; k0 += 128) {   // 8 iterations
        float4 xv[4];
#pragma unroll
        for (int r = 0; r < 4; r++) {
            xv[r] = *(const float4*)(x + (size_t)(m0 + r) * K_DIM + k0);
            __half2 h0 = __floats2half2_rn(xv[r].x, xv[r].y);
            __half2 h1 = __floats2half2_rn(xv[r].z, xv[r].w);
            float2 pk;
            pk.x = __uint_as_float(*(const uint32_t*)&h0);
            pk.y = __uint_as_float(*(const uint32_t*)&h1);
            *(float2*)(g_xh + (size_t)(m0 + r) * K_DIM + k0) = pk;
        }
#pragma unroll
        for (int d = 0; d < 4; d++) {
            const size_t kk = (size_t)(k0 + d) * 8;
            float4 a0 = *(const float4*)(aq + kk);
            float4 a1 = *(const float4*)(aq + kk + 4);
            float4 v0 = *(const float4*)(av + kk);
            float4 v1 = *(const float4*)(av + kk + 4);
#pragma unroll
            for (int r = 0; r < 4; r++) {
                const float s = (d == 0) ? xv[r].x : (d == 1) ? xv[r].y
                              : (d == 2) ? xv[r].z : xv[r].w;
                acc[r][0]  += s * a0.x; acc[r][1]  += s * a0.y;
                acc[r][2]  += s * a0.z; acc[r][3]  += s * a0.w;
                acc[r][4]  += s * a1.x; acc[r][5]  += s * a1.y;
                acc[r][6]  += s * a1.z; acc[r][7]  += s * a1.w;
                acc[r][8]  += s * v0.x; acc[r][9]  += s * v0.y;
                acc[r][10] += s * v0.z; acc[r][11] += s * v0.w;
                acc[r][12] += s * v1.x; acc[r][13] += s * v1.y;
                acc[r][14] += s * v1.z; acc[r][15] += s * v1.w;
            }
        }
    }
#pragma unroll
    for (int r = 0; r < 4; r++) {
#pragma unroll
        for (int j = 0; j < 16; j++) {
            float s = acc[r][j];
            s += __shfl_xor_sync(0xffffffffu, s, 16);
            s += __shfl_xor_sync(0xffffffffu, s, 8);
            s += __shfl_xor_sync(0xffffffffu, s, 4);
            s += __shfl_xor_sync(0xffffffffu, s, 2);
            s += __shfl_xor_sync(0xffffffffu, s, 1);
            acc[r][j] = s;
        }
        if (lid == 0) {
            float4* o = (float4*)(g_T + (size_t)(m0 + r) * 16);
            o[0] = make_float4(acc[r][0],  acc[r][1],  acc[r][2],  acc[r][3]);
            o[1] = make_float4(acc[r][4],  acc[r][5],  acc[r][6],  acc[r][7]);
            o[2] = make_float4(acc[r][8],  acc[r][9],  acc[r][10], acc[r][11]);
            o[3] = make_float4(acc[r][12], acc[r][13], acc[r][14], acc[r][15]);
        }
    }
}

// ---------------- main GEMM ----------------
__device__ __forceinline__ void load_chunk(char* stage, int m0, int n0, int kc) {
    const int t = threadIdx.x;
    const int col0 = kc * KC;
    uint32_t sA = smem_u32(stage);
    uint32_t sB = sA + TILE_B;
#pragma unroll
    for (int i = 0; i < 4; i++) {
        int j   = t + i * 256;      // 0..1023 : 16B segments of a 128x64 fp16 tile
        int row = j >> 3;
        int seg = j & 7;
        uint32_t off = (uint32_t)(row * ROW_B + seg * 16);
        cp_async16(sA + off, g_xh + (size_t)(m0 + row) * K_DIM + col0 + seg * 8);
        cp_async16(sB + off, g_wh + (size_t)(n0 + row) * K_DIM + col0 + seg * 8);
    }
}

__global__ void __launch_bounds__(256, 2)
gemm_kernel(const float* __restrict__ bias,
            const float* __restrict__ Bq_pool,
            const float* __restrict__ Bv_pool,
            const int* __restrict__ idx,
            float* __restrict__ out) {
    extern __shared__ char smem[];
    const int tid = threadIdx.x;
    const int wid = tid >> 5;
    const int lid = tid & 31;
    const int wm  = wid & 1;       // 2 warps in M  (64 rows each)
    const int wn  = wid >> 1;      // 4 warps in N  (32 cols each)
    const int n0  = blockIdx.x * TN;
    const int m0  = blockIdx.y * TM;
    const int region = blockIdx.x >> 3;   // 0=q, 1=k, 2=v

    // ---- epilogue constants ----
    float* sh_bias = (float*)(smem + SM_BIAS);
    float* sh_B    = (float*)(smem + SM_EPB);
    if (tid < 128) sh_bias[tid] = bias[n0 + tid];
    const int pool_i = idx[blockIdx.y >> 5];   // 32 M-tiles (128 rows) per batch
    if (region != 1) {
        const float* Bp = (region == 0) ? (Bq_pool + (size_t)pool_i * POOL_RK * K_DIM)
                                        : (Bv_pool + (size_t)pool_i * POOL_RK * K_DIM);
        int colbase = (region == 0) ? n0 : (n0 - 2048);
#pragma unroll
        for (int e = tid; e < 1024; e += 256) {
            int r = e >> 7, c = e & 127;
            sh_B[e] = Bp[(size_t)r * K_DIM + colbase + c];
        }
    }

    // ---- accumulators ----
    float acc[4][4][4];
#pragma unroll
    for (int i = 0; i < 4; i++)
#pragma unroll
        for (int j = 0; j < 4; j++)
#pragma unroll
            for (int c = 0; c < 4; c++) acc[i][j][c] = 0.f;

    // per-thread ldmatrix source offsets
    const int a_row = (lid & 15);
    const int a_kh  = (lid >> 4) * 8;
    const int b_row = (lid & 7) + ((lid >> 4) << 3);
    const int b_kh  = ((lid >> 3) & 1) * 8;

    // ---- pipeline prologue: 2 stages in flight ----
    load_chunk(smem + SM_STAGE + 0 * STAGE_B, m0, n0, 0); CP_COMMIT();
    load_chunk(smem + SM_STAGE + 1 * STAGE_B, m0, n0, 1); CP_COMMIT();

    // ---- main K loop: one barrier per iteration ----
    for (int kc = 0; kc < NK; kc++) {
        if (kc == NK - 1) cp_wait<0>(); else cp_wait<1>();
        __syncthreads();
        // All warps are past compute of kc-1 => stage (kc+2)%3 (read at kc-1) is free.

        int kn = kc + 2;
        if (kn < NK) {
            load_chunk(smem + SM_STAGE + (kn % NSTAGE) * STAGE_B, m0, n0, kn);
            CP_COMMIT();
        }

        char* stage = smem + SM_STAGE + (kc % NSTAGE) * STAGE_B;
        uint32_t sA = smem_u32(stage);
        uint32_t sB = sA + TILE_B;
#pragma unroll
        for (int ks = 0; ks < 4; ks++) {
            const int k0 = ks * 16;
            uint32_t a[4][4];
#pragma unroll
            for (int am = 0; am < 4; am++) {
                uint32_t addr = sA + (uint32_t)((wm * 64 + am * 16 + a_row) * ROW_B
                                                + (k0 + a_kh) * 2);
                ldm_x4(a[am][0], a[am][1], a[am][2], a[am][3], addr);
            }
            uint32_t b[2][4];
#pragma unroll
            for (int g = 0; g < 2; g++) {
                uint32_t addr = sB + (uint32_t)((wn * 32 + g * 16 + b_row) * ROW_B
                                                + (k0 + b_kh) * 2);
                ldm_x4(b[g][0], b[g][1], b[g][2], b[g][3], addr);
            }
#pragma unroll
            for (int am = 0; am < 4; am++)
#pragma unroll
                for (int an = 0; an < 4; an++) {
                    uint32_t bb[2] = { b[an >> 1][(an & 1) * 2],
                                       b[an >> 1][(an & 1) * 2 + 1] };
                    mma16816(acc[am][an], a[am], bb);
                }
        }
    }

    // ---- epilogue: bias + LoRA + store ----
    const bool lora = (region != 1);
    const int tq = lid >> 2;          // 0..7
    const int tr = lid & 3;           // 0..3
#pragma unroll
    for (int am = 0; am < 4; am++) {
#pragma unroll
        for (int h = 0; h < 2; h++) {
            const int lrow = wm * 64 + am * 16 + tq + h * 8;
            const size_t m = (size_t)(m0 + lrow);
            float t[8];
            if (lora) {
                const float* Tp = g_T + m * 16 + (region == 2 ? 8 : 0);
                float4 t0 = *(const float4*)Tp;
                float4 t1 = *(const float4*)(Tp + 4);
                t[0] = t0.x; t[1] = t0.y; t[2] = t0.z; t[3] = t0.w;
                t[4] = t1.x; t[5] = t1.y; t[6] = t1.z; t[7] = t1.w;
            }
#pragma unroll
            for (int an = 0; an < 4; an++) {
                const int lc = wn * 32 + an * 8 + tr * 2;
                float v0 = acc[am][an][h * 2 + 0] + sh_bias[lc];
                float v1 = acc[am][an][h * 2 + 1] + sh_bias[lc + 1];
                if (lora) {
#pragma unroll
                    for (int rr = 0; rr < 8; rr++) {
                        v0 += t[rr] * sh_B[rr * 128 + lc];
                        v1 += t[rr] * sh_B[rr * 128 + lc + 1];
                    }
                }
                *(float2*)(out + m * N_DIM + n0 + lc) = make_float2(v0, v1);
            }
        }
    }
}

// ---------------- launch ----------------
extern "C" void kernel_launch(void* const* d_in, const int* in_sizes, int n_in,
                              void* d_out, int out_size) {
    (void)in_sizes; (void)n_in; (void)out_size;
    const float* x    = (const float*)d_in[0];
    const float* w    = (const float*)d_in[1];
    const float* bias = (const float*)d_in[2];
    const float* Aq   = (const float*)d_in[3];
    const float* Bq   = (const float*)d_in[4];
    const float* Av   = (const float*)d_in[5];
    const float* Bv   = (const float*)d_in[6];
    const int*   idx  = (const int*)d_in[7];
    float* out = (float*)d_out;

    static bool attr_set = false;
    if (!attr_set) {
        cudaFuncSetAttribute(gemm_kernel, cudaFuncAttributeMaxDynamicSharedMemorySize,
                             SM_TOTAL);
        attr_set = true;
    }

    const size_t w4 = (size_t)N_DIM * K_DIM / 4;
    cvt_w_kernel<<<(unsigned)((w4 + 255) / 256), 256>>>(w);
    cvt_lora_kernel<<<M_TOT / 4 / 8, 256>>>(x, Aq, Av, idx);

    dim3 grid(N_DIM / TN, M_TOT / TM, 1);
    gemm_kernel<<<grid, 256, SM_TOTAL>>>(bias, Bq, Bv, idx, out);
}